// round 11
// baseline (speedup 1.0000x reference)
#include <cuda_runtime.h>
#include <cuda_bf16.h>
#include <math.h>
#include <stdint.h>

// ---- problem constants ----
#define BB 4
#define NN 2048
#define DD 512
#define EE 8
#define HH 1365
#define TWOH 2730
#define CAP 320
#define BN (BB*NN)        // 8192
#define BE (BB*EE)        // 32
#define SLOTS (BE*CAP)    // 10240
#define ACTS 1376         // padded act row stride (43 chunks of 32)
#define W1N 1408          // padded n rows of each w1 half (u/g)
#define W1KP 256          // k-pairs of w1
#define W2KP 688          // padded k-pairs of w2 (683 used)

// ---- scratch ----
__device__ __align__(16) uint32_t g_xgh[BN*DD/2];          // bf16x2 RMS-normed input
__device__ __align__(16) uint32_t g_acth[(SLOTS*ACTS)/2];  // bf16x2 GEGLU activations
__device__ __align__(16) uint32_t g_w1h[(size_t)EE*2*W1N*W1KP]; // [e][h][n][kp]
__device__ __align__(16) uint32_t g_w2h[(size_t)EE*512*W2KP];   // [e][n][kp]
__device__ float g_eo[SLOTS*DD];
__device__ int   g_slot_tok[SLOTS];
__device__ int   g_e1[BN], g_e2[BN];
__device__ float g_g1[BN], g_g2[BN];
__device__ int   g_c1[BN], g_c2[BN];
__device__ unsigned char g_r2[BN];
__device__ int   g_total0[BE];
__device__ float g_dp[BE];
__device__ float g_zsum;

// ================= helpers =================
__device__ __forceinline__ uint32_t pack2(float lo, float hi){
    __nv_bfloat162 h = __floats2bfloat162_rn(lo, hi);
    return *reinterpret_cast<uint32_t*>(&h);
}
__device__ __forceinline__ void mma16(float* c,
        uint32_t a0, uint32_t a1, uint32_t a2, uint32_t a3,
        uint32_t b0, uint32_t b1){
    asm volatile(
        "mma.sync.aligned.m16n8k16.row.col.f32.bf16.bf16.f32 "
        "{%0,%1,%2,%3},{%4,%5,%6,%7},{%8,%9},{%0,%1,%2,%3};"
        : "+f"(c[0]), "+f"(c[1]), "+f"(c[2]), "+f"(c[3])
        : "r"(a0), "r"(a1), "r"(a2), "r"(a3), "r"(b0), "r"(b1));
}
__device__ __forceinline__ uint32_t s2u(const void* p){
    return (uint32_t)__cvta_generic_to_shared(p);
}
__device__ __forceinline__ void cp16(uint32_t saddr, const void* g){
    asm volatile("cp.async.cg.shared.global [%0], [%1], 16;" :: "r"(saddr), "l"(g));
}
#define CP_COMMIT() asm volatile("cp.async.commit_group;")
#define CP_WAIT1()  asm volatile("cp.async.wait_group 1;")
#define LDMX4(r0,r1,r2,r3,addr) \
    asm volatile("ldmatrix.sync.aligned.m8n8.x4.shared.b16 {%0,%1,%2,%3},[%4];" \
        : "=r"(r0),"=r"(r1),"=r"(r2),"=r"(r3) : "r"(addr))

// ================= threefry2x32 (JAX-compatible) =================
__device__ __forceinline__ uint32_t rotl32(uint32_t v, int r){ return (v<<r)|(v>>(32-r)); }
__device__ __forceinline__ void threefry2x32(uint32_t k0, uint32_t k1,
                                             uint32_t x0, uint32_t x1,
                                             uint32_t &o0, uint32_t &o1){
    uint32_t ks0 = k0, ks1 = k1, ks2 = 0x1BD11BDAu ^ k0 ^ k1;
    x0 += ks0; x1 += ks1;
#define TF_RND(r) { x0 += x1; x1 = rotl32(x1,(r)); x1 ^= x0; }
    TF_RND(13) TF_RND(15) TF_RND(26) TF_RND(6);  x0 += ks1; x1 += ks2 + 1u;
    TF_RND(17) TF_RND(29) TF_RND(16) TF_RND(24); x0 += ks2; x1 += ks0 + 2u;
    TF_RND(13) TF_RND(15) TF_RND(26) TF_RND(6);  x0 += ks0; x1 += ks1 + 3u;
    TF_RND(17) TF_RND(29) TF_RND(16) TF_RND(24); x0 += ks1; x1 += ks2 + 4u;
    TF_RND(13) TF_RND(15) TF_RND(26) TF_RND(6);  x0 += ks2; x1 += ks0 + 5u;
#undef TF_RND
    o0 = x0; o1 = x1;
}
__device__ __forceinline__ float bits_to_uniform(uint32_t b){
    return __uint_as_float((b >> 9) | 0x3f800000u) - 1.0f;
}

// ================= init scratch =================
__global__ void k_init(){
    int i = blockIdx.x * blockDim.x + threadIdx.x;
    int stride = gridDim.x * blockDim.x;
    for (int j = i; j < SLOTS; j += stride) g_slot_tok[j] = -1;
    for (int j = i; j < BN; j += stride){ g_c1[j] = -1; g_c2[j] = -1; }
    if (i < BE){ g_total0[i] = 0; g_dp[i] = 0.f; }
    if (i == 0) g_zsum = 0.f;
}

// ================= weight conversion (n-major, k-pair packed) =================
// w1 [e][k=512][2730] -> g_w1h [e][h][n=1408][kp=256]
__global__ void k_conv1(const float* __restrict__ w1){
    int idx = blockIdx.x * 256 + threadIdx.x;
    if (idx >= EE*2*W1N*(W1KP/4)) return;
    int n = idx % W1N; int r = idx / W1N;
    int kp4 = (r % (W1KP/4)) * 4; r /= (W1KP/4);
    int h = r & 1; int e = r >> 1;
    const float* base = w1 + (size_t)e*DD*TWOH + (h ? HH : 0) + n;
    uint32_t o[4];
    bool ok = (n < HH);
#pragma unroll
    for (int i = 0; i < 4; i++){
        int k = 2*(kp4 + i);
        float lo = ok ? base[(size_t)k*TWOH]       : 0.f;
        float hi = ok ? base[(size_t)(k+1)*TWOH]   : 0.f;
        o[i] = pack2(lo, hi);
    }
    *reinterpret_cast<uint4*>(
        &g_w1h[(((size_t)e*2 + h)*W1N + n)*W1KP + kp4]) = make_uint4(o[0],o[1],o[2],o[3]);
}

// w2 [e][k=1365][512] -> g_w2h [e][n=512][kp=688]
__global__ void k_conv2(const float* __restrict__ w2){
    int idx = blockIdx.x * 256 + threadIdx.x;
    if (idx >= EE*512*(W2KP/4)) return;
    int n = idx % 512; int r = idx / 512;
    int kp4 = (r % (W2KP/4)) * 4; int e = r / (W2KP/4);
    const float* base = w2 + (size_t)e*HH*DD + n;
    uint32_t o[4];
#pragma unroll
    for (int i = 0; i < 4; i++){
        int k = 2*(kp4 + i);
        float lo = (k < HH)     ? base[(size_t)k*DD]     : 0.f;
        float hi = (k+1 < HH)   ? base[(size_t)(k+1)*DD] : 0.f;
        o[i] = pack2(lo, hi);
    }
    *reinterpret_cast<uint4*>(
        &g_w2h[((size_t)e*512 + n)*W2KP + kp4]) = make_uint4(o[0],o[1],o[2],o[3]);
}

// ================= K1: RMS norm + router (smem gw^T) =================
__global__ __launch_bounds__(256) void k_gate(const float* __restrict__ x,
                                              const float* __restrict__ gw,
                                              const float* __restrict__ png){
    __shared__ float sGT[8][516];
    __shared__ float sPn[512];
    __shared__ float s_p[8][8];
    __shared__ float s_z[8];
    int tid = threadIdx.x;
    int wib  = tid >> 5;
    int lane = tid & 31;
    int t    = blockIdx.x * 8 + wib;
    int bblk = (blockIdx.x * 8) / NN;

#pragma unroll
    for (int i = 0; i < 16; i++){
        int idx = i*256 + tid;
        sGT[idx & 7][idx >> 3] = gw[idx];
    }
    sPn[tid]       = png[tid];
    sPn[tid + 256] = png[tid + 256];
    __syncthreads();

    const float* xr = x + (size_t)t * DD;
    float4 v[4];
    float ss = 0.f;
#pragma unroll
    for (int j = 0; j < 4; j++){
        int d4 = (j*32 + lane) * 4;
        v[j] = *reinterpret_cast<const float4*>(xr + d4);
        ss += v[j].x*v[j].x + v[j].y*v[j].y + v[j].z*v[j].z + v[j].w*v[j].w;
    }
#pragma unroll
    for (int off = 16; off; off >>= 1) ss += __shfl_xor_sync(0xffffffffu, ss, off);
    float nrm = sqrtf(ss); nrm = fmaxf(nrm, 1e-12f);
    float scale = 22.62741699796952f / nrm;

    float xv[4][4];
#pragma unroll
    for (int j = 0; j < 4; j++){
        int d4 = (j*32 + lane) * 4;
        float4 pv = *reinterpret_cast<const float4*>(&sPn[d4]);
        xv[j][0] = v[j].x*scale*pv.x; xv[j][1] = v[j].y*scale*pv.y;
        xv[j][2] = v[j].z*scale*pv.z; xv[j][3] = v[j].w*scale*pv.w;
        uint2 pw = make_uint2(pack2(xv[j][0], xv[j][1]), pack2(xv[j][2], xv[j][3]));
        *reinterpret_cast<uint2*>(&g_xgh[((size_t)t*DD + d4) >> 1]) = pw;
    }

    float acc[8];
#pragma unroll
    for (int e = 0; e < 8; e++){
        float a = 0.f;
#pragma unroll
        for (int j = 0; j < 4; j++){
            int d4 = (j*32 + lane) * 4;
            float4 g4 = *reinterpret_cast<const float4*>(&sGT[e][d4]);
            a = fmaf(xv[j][0], g4.x, a); a = fmaf(xv[j][1], g4.y, a);
            a = fmaf(xv[j][2], g4.z, a); a = fmaf(xv[j][3], g4.w, a);
        }
        acc[e] = a;
    }
#pragma unroll
    for (int e = 0; e < 8; e++)
#pragma unroll
        for (int off = 16; off; off >>= 1)
            acc[e] += __shfl_xor_sync(0xffffffffu, acc[e], off);

    if (lane == 0){
        float m = acc[0];
#pragma unroll
        for (int e = 1; e < 8; e++) m = fmaxf(m, acc[e]);
        float p[8], s = 0.f;
#pragma unroll
        for (int e = 0; e < 8; e++){ p[e] = expf(acc[e]-m); s += p[e]; }
        float inv = 1.f / s;
        int e1 = 0; float v1 = p[0]*inv;
        int e2 = -1; float v2 = -1.f;
#pragma unroll
        for (int e = 1; e < 8; e++){
            float pe = p[e]*inv;
            if (pe > v1){ v2 = v1; e2 = e1; v1 = pe; e1 = e; }
            else if (pe > v2){ v2 = pe; e2 = e; }
        }
        float denom = fmaxf(v1+v2, 1e-9f);
        float gg1 = v1/denom, gg2 = v2/denom;
        uint32_t y0, y1;
        threefry2x32(0u, 42u, (uint32_t)t, (uint32_t)(t + 8192), y0, y1);
        float u1 = bits_to_uniform(y1);
        unsigned char r2 = (u1 < (gg2 / 0.2f)) ? 1 : 0;

        g_e1[t] = e1; g_e2[t] = e2;
        g_g1[t] = gg1; g_g2[t] = gg2; g_r2[t] = r2;
        atomicAdd(&g_total0[bblk*8 + e1], 1);
        float z = m + logf(s);
        s_z[wib] = z*z;
#pragma unroll
        for (int e = 0; e < 8; e++) s_p[wib][e] = p[e]*inv;
    }
    __syncthreads();
    if (tid < 8){
        float a = 0.f;
#pragma unroll
        for (int w = 0; w < 8; w++) a += s_p[w][tid];
        atomicAdd(&g_dp[bblk*8 + tid], a);
    } else if (tid == 8){
        float a = 0.f;
#pragma unroll
        for (int w = 0; w < 8; w++) a += s_z[w];
        atomicAdd(&g_zsum, a);
    }
}

// ================= K2: capacity scan =================
__global__ void k_scan(){
    int w = threadIdx.x >> 5;
    int lane = threadIdx.x & 31;
    int b = w >> 3, e = w & 7;
    int be = b*EE + e;
    int base1 = min(g_total0[be], CAP);
    int c0 = 0, c1 = 0;
    for (int n0 = 0; n0 < NN; n0 += 32){
        int n = n0 + lane;
        int t = b*NN + n;
        int m0 = (g_e1[t] == e);
        int m1 = (g_e2[t] == e) && g_r2[t];
        unsigned bal0 = __ballot_sync(0xffffffffu, m0);
        unsigned bal1 = __ballot_sync(0xffffffffu, m1);
        unsigned lt = (1u << lane) - 1u;
        if (m0){
            int pos = c0 + __popc(bal0 & lt);
            if (pos < CAP){ g_c1[t] = pos; g_slot_tok[be*CAP + pos] = n; }
            else g_c1[t] = -1;
        }
        if (m1){
            int pos = c1 + __popc(bal1 & lt) + base1;
            if (pos < CAP){ g_c2[t] = pos; g_slot_tok[be*CAP + pos] = n; }
            else g_c2[t] = -1;
        }
        c0 += __popc(bal0); c1 += __popc(bal1);
    }
}

// ================= K3: GEMM1 (bf16 mma, all-ldmatrix, 3-stage cp.async) =========
// dyn smem: uA 3*[64][20] | uBu 3*[128][20] | uBg 3*[128][20] = 76800 B
__global__ __launch_bounds__(256) void k_gemm1(const float* __restrict__ b1,
                                               const float* __restrict__ mb){
    extern __shared__ uint32_t dsm[];
    uint32_t* uA  = dsm;              // [s][m=64][20]
    uint32_t* uBu = dsm + 3*1280;     // [s][n=128][20]
    uint32_t* uBg = uBu + 3*2560;
    __shared__ int sTok[64];

    int be = blockIdx.z, b = be >> 3, e = be & 7;
    int m0 = blockIdx.y * 64, n0 = blockIdx.x * 128;
    int tid = threadIdx.x;
    if (tid < 64) sTok[tid] = g_slot_tok[be*CAP + m0 + tid];
    __syncthreads();

    int lane = tid & 31, wid = tid >> 5;
    int group = lane >> 2, tig = lane & 3;
    int wm = wid >> 2, wn = wid & 3;

    // A-load indices
    int amr = tid & 63;
    int akb = (tid >> 6) * 8;
    int tokA = sTok[amr];
    const uint32_t* aSrc = (tokA >= 0)
        ? &g_xgh[((size_t)(b*NN + tokA)*DD + akb) >> 1] : nullptr;
    // B-load indices: 4 threads per n row (64 rows per pass, 2 passes)
    int brow = tid >> 2;               // 0..63
    int bseg = (tid & 3) * 4;          // u32 offset in kp
    const uint32_t* Wu = g_w1h + ((size_t)e*2    )*W1N*W1KP;
    const uint32_t* Wg = g_w1h + ((size_t)e*2 + 1)*W1N*W1KP;

    // B-fragment ldmatrix lane addressing (q covers ni pair 2q,2q+1)
    int blRow = wn*32 + ((lane>>4)&1)*8 + (lane&7);   // + q*16
    int blCol = ((lane>>3)&1)*4;                       // + kpb

    if (tokA < 0){
#pragma unroll
        for (int s = 0; s < 3; s++)
            *reinterpret_cast<uint4*>(uA + s*1280 + amr*20 + (akb>>1)) = make_uint4(0,0,0,0);
    }

    float cu[2][4][4], cg[2][4][4];
#pragma unroll
    for (int i = 0; i < 2; i++)
#pragma unroll
        for (int j = 0; j < 4; j++)
#pragma unroll
            for (int r = 0; r < 4; r++){ cu[i][j][r] = 0.f; cg[i][j][r] = 0.f; }

#define G1_STAGE(s, cidx) {                                                       \
    if (aSrc) cp16(s2u(uA + (s)*1280 + amr*20 + (akb>>1)), aSrc + (cidx)*16);     \
    _Pragma("unroll")                                                             \
    for (int it = 0; it < 2; it++){                                               \
        int rl = it*64 + brow;                                                    \
        size_t gsrc = (size_t)(n0 + rl)*W1KP + (cidx)*16 + bseg;                  \
        cp16(s2u(uBu + (s)*2560 + rl*20 + bseg), Wu + gsrc);                      \
        cp16(s2u(uBg + (s)*2560 + rl*20 + bseg), Wg + gsrc);                      \
    } }

    const int NC = DD/32;   // 16
    G1_STAGE(0, 0); CP_COMMIT();
    G1_STAGE(1, 1); CP_COMMIT();
    for (int c = 0; c < NC; c++){
        CP_WAIT1();
        __syncthreads();
        int s = c % 3;
        uint32_t* pA  = uA  + s*1280;
        uint32_t* pBu = uBu + s*2560;
        uint32_t* pBg = uBg + s*2560;
#pragma unroll
        for (int ks = 0; ks < 2; ks++){
            int kpb = ks * 8;
            uint32_t a[2][4];
#pragma unroll
            for (int mi = 0; mi < 2; mi++){
                int row = wm*32 + mi*16 + (lane & 15);
                uint32_t addr = s2u(pA + row*20 + kpb + ((lane >> 4) << 2));
                LDMX4(a[mi][0], a[mi][1], a[mi][2], a[mi][3], addr);
            }
            uint32_t bu[2][4], bg[2][4];
#pragma unroll
            for (int q = 0; q < 2; q++){
                uint32_t au_ = s2u(pBu + (blRow + q*16)*20 + blCol + kpb);
                uint32_t ag_ = s2u(pBg + (blRow + q*16)*20 + blCol + kpb);
                LDMX4(bu[q][0], bu[q][1], bu[q][2], bu[q][3], au_);
                LDMX4(bg[q][0], bg[q][1], bg[q][2], bg[q][3], ag_);
            }
#pragma unroll
            for (int ni = 0; ni < 4; ni++){
                int q = ni >> 1, r2i = (ni & 1) * 2;
#pragma unroll
                for (int mi = 0; mi < 2; mi++){
                    mma16(cu[mi][ni], a[mi][0],a[mi][1],a[mi][2],a[mi][3],
                          bu[q][r2i], bu[q][r2i+1]);
                    mma16(cg[mi][ni], a[mi][0],a[mi][1],a[mi][2],a[mi][3],
                          bg[q][r2i], bg[q][r2i+1]);
                }
            }
        }
        int nx = c + 2;
        if (nx < NC){ G1_STAGE(nx % 3, nx); }
        CP_COMMIT();
    }
#undef G1_STAGE

    // ---- GEGLU epilogue: packed bf16 pairs ----
    const float* b1e = b1 + (size_t)e * TWOH;
    const float* mbe = mb + (size_t)e * HH;
#pragma unroll
    for (int mi = 0; mi < 2; mi++){
#pragma unroll
        for (int rp = 0; rp < 2; rp++){
            int row = m0 + wm*32 + mi*16 + group + rp*8;
            size_t rowoff = ((size_t)be*CAP + row) * ACTS;
#pragma unroll
            for (int ni = 0; ni < 4; ni++){
                int col = n0 + wn*32 + ni*8 + tig*2;
                if (col < ACTS){
                    float lo = 0.f, hi = 0.f;
                    if (col < HH){
                        float u  = cu[mi][ni][rp*2]   + b1e[col];
                        float gv = cg[mi][ni][rp*2]   + b1e[col + HH];
                        lo = u * (0.5f * gv * (1.f + erff(gv * 0.7071067811865476f))) * mbe[col];
                    }
                    if (col + 1 < HH){
                        float u  = cu[mi][ni][rp*2+1] + b1e[col+1];
                        float gv = cg[mi][ni][rp*2+1] + b1e[col+1 + HH];
                        hi = u * (0.5f * gv * (1.f + erff(gv * 0.7071067811865476f))) * mbe[col+1];
                    }
                    g_acth[(rowoff + col) >> 1] = pack2(lo, hi);
                }
            }
        }
    }
}

// ================= K4: GEMM2 (bf16 mma, all-ldmatrix, 3-stage cp.async) =========
__global__ __launch_bounds__(256) void k_gemm2(const float* __restrict__ b2){
    __shared__ uint32_t sA[3][64][20];
    __shared__ uint32_t sB[3][128][20];

    int be = blockIdx.z, e = be & 7;
    int m0 = blockIdx.y * 64, n0 = blockIdx.x * 128;
    int tid = threadIdx.x;
    int lane = tid & 31, wid = tid >> 5;
    int group = lane >> 2, tig = lane & 3;
    int wm = wid >> 2, wn = wid & 3;

    int amr = tid & 63;
    int akb = (tid >> 6) * 8;
    const uint32_t* aSrc = &g_acth[(((size_t)be*CAP + m0 + amr)*ACTS + akb) >> 1];
    int brow = tid >> 2;
    int bseg = (tid & 3) * 4;
    const uint32_t* Wn = g_w2h + (size_t)e*512*W2KP;

    int blRow = wn*32 + ((lane>>4)&1)*8 + (lane&7);
    int blCol = ((lane>>3)&1)*4;

    float cc[2][4][4];
#pragma unroll
    for (int i = 0; i < 2; i++)
#pragma unroll
        for (int j = 0; j < 4; j++)
#pragma unroll
            for (int r = 0; r < 4; r++) cc[i][j][r] = 0.f;

#define G2_STAGE(s, cidx) {                                                       \
    cp16(s2u(&sA[s][amr][akb>>1]), aSrc + (cidx)*16);                             \
    _Pragma("unroll")                                                             \
    for (int it = 0; it < 2; it++){                                               \
        int rl = it*64 + brow;                                                    \
        cp16(s2u(&sB[s][rl][bseg]), Wn + (size_t)(n0 + rl)*W2KP + (cidx)*16 + bseg);\
    } }

    const int NC = ACTS/32;   // 43
    G2_STAGE(0, 0); CP_COMMIT();
    G2_STAGE(1, 1); CP_COMMIT();
    for (int c = 0; c < NC; c++){
        CP_WAIT1();
        __syncthreads();
        int s = c % 3;
#pragma unroll
        for (int ks = 0; ks < 2; ks++){
            int kpb = ks * 8;
            uint32_t a[2][4];
#pragma unroll
            for (int mi = 0; mi < 2; mi++){
                int row = wm*32 + mi*16 + (lane & 15);
                uint32_t addr = s2u(&sA[s][row][kpb + ((lane >> 4) << 2)]);
                LDMX4(a[mi][0], a[mi][1], a[mi][2], a[mi][3], addr);
            }
            uint32_t bb[2][4];
#pragma unroll
            for (int q = 0; q < 2; q++){
                uint32_t ad_ = s2u(&sB[s][blRow + q*16][blCol + kpb]);
                LDMX4(bb[q][0], bb[q][1], bb[q][2], bb[q][3], ad_);
            }
#pragma unroll
            for (int ni = 0; ni < 4; ni++){
                int q = ni >> 1, r2i = (ni & 1) * 2;
#pragma unroll
                for (int mi = 0; mi < 2; mi++)
                    mma16(cc[mi][ni], a[mi][0],a[mi][1],a[mi][2],a[mi][3],
                          bb[q][r2i], bb[q][r2i+1]);
            }
        }
        int nx = c + 2;
        if (nx < NC){ G2_STAGE(nx % 3, nx); }
        CP_COMMIT();
    }
#undef G2_STAGE

    const float* b2e = b2 + (size_t)e * DD;
#pragma unroll
    for (int mi = 0; mi < 2; mi++){
#pragma unroll
        for (int rp = 0; rp < 2; rp++){
            int row = m0 + wm*32 + mi*16 + group + rp*8;
            float* orow = &g_eo[((size_t)be*CAP + row) * DD];
#pragma unroll
            for (int ni = 0; ni < 4; ni++){
                int col = n0 + wn*32 + ni*8 + tig*2;
                orow[col]   = cc[mi][ni][rp*2]   + b2e[col];
                orow[col+1] = cc[mi][ni][rp*2+1] + b2e[col+1];
            }
        }
    }
}

// ================= K5: combine + residual + LayerNorm =================
__global__ __launch_bounds__(256) void k_combine(const float* __restrict__ x,
                                                 const float* __restrict__ lng,
                                                 const float* __restrict__ lnb,
                                                 float* __restrict__ out){
    int t = blockIdx.x * 8 + (threadIdx.x >> 5);
    int lane = threadIdx.x & 31;
    int b = t / NN;
    int c1 = g_c1[t], c2 = g_c2[t];
    float w1g = (c1 >= 0) ? g_g1[t] : 0.f;
    float w2g = (c2 >= 0) ? g_g2[t] : 0.f;
    const float* eo1 = &g_eo[(((size_t)(b*EE + g_e1[t]))*CAP + (c1 >= 0 ? c1 : 0)) * DD];
    const float* eo2 = &g_eo[(((size_t)(b*EE + g_e2[t]))*CAP + (c2 >= 0 ? c2 : 0)) * DD];
    const float* xr = x + (size_t)t * DD;

    float y[16];
    float s = 0.f, s2 = 0.f;
#pragma unroll
    for (int j = 0; j < 4; j++){
        int d4 = (j*32 + lane) * 4;
        float4 xv = *reinterpret_cast<const float4*>(xr + d4);
        float4 a  = *reinterpret_cast<const float4*>(eo1 + d4);
        float4 c  = *reinterpret_cast<const float4*>(eo2 + d4);
        float yv[4] = { xv.x + w1g*a.x + w2g*c.x,
                        xv.y + w1g*a.y + w2g*c.y,
                        xv.z + w1g*a.z + w2g*c.z,
                        xv.w + w1g*a.w + w2g*c.w };
#pragma unroll
        for (int q = 0; q < 4; q++){
            y[j*4+q] = yv[q];
            s += yv[q]; s2 += yv[q]*yv[q];
        }
    }
#pragma unroll
    for (int off = 16; off; off >>= 1){
        s  += __shfl_xor_sync(0xffffffffu, s,  off);
        s2 += __shfl_xor_sync(0xffffffffu, s2, off);
    }
    float mu = s * (1.f/512.f);
    float var = s2 * (1.f/512.f) - mu*mu;
    float iv = rsqrtf(var + 1e-5f);
#pragma unroll
    for (int j = 0; j < 4; j++){
        int d4 = (j*32 + lane) * 4;
        float4 gv = *reinterpret_cast<const float4*>(lng + d4);
        float4 bv = *reinterpret_cast<const float4*>(lnb + d4);
        float4 ov;
        ov.x = (y[j*4+0]-mu)*iv*gv.x + bv.x;
        ov.y = (y[j*4+1]-mu)*iv*gv.y + bv.y;
        ov.z = (y[j*4+2]-mu)*iv*gv.z + bv.z;
        ov.w = (y[j*4+3]-mu)*iv*gv.w + bv.w;
        *reinterpret_cast<float4*>(out + (size_t)t*DD + d4) = ov;
    }
}

// ================= K6: aux losses =================
__global__ void k_aux(float* __restrict__ out, int out_size){
    if (out_size <= BN*DD) return;
    float bal = 0.f;
    for (int be = 0; be < BE; be++){
        float dp = g_dp[be] * (1.f/(float)NN);
        float d1 = (float)min(g_total0[be], CAP) * (1.f/(float)NN);
        bal += dp * d1;
    }
    bal = bal * (1.f/(float)BE) * (float)(EE*EE);
    float zz = g_zsum * (1.f/(float)BN);
    out[BN*DD] = 0.01f * bal + 0.001f * zz;
}

// ================= launch =================
extern "C" void kernel_launch(void* const* d_in, const int* in_sizes, int n_in,
                              void* d_out, int out_size){
    const float* x    = (const float*)d_in[0];
    const float* gw   = (const float*)d_in[1];
    const float* png  = (const float*)d_in[2];
    const float* w1   = (const float*)d_in[3];
    const float* b1   = (const float*)d_in[4];
    const float* mb   = (const float*)d_in[5];
    const float* w2   = (const float*)d_in[6];
    const float* b2   = (const float*)d_in[7];
    const float* lng  = (const float*)d_in[8];
    const float* lnb  = (const float*)d_in[9];
    float* out = (float*)d_out;

    const int G1_SMEM = (3*1280 + 3*2560 + 3*2560) * 4;   // 76800 B
    static bool attr_set = false;
    if (!attr_set){
        cudaFuncSetAttribute(k_gemm1, cudaFuncAttributeMaxDynamicSharedMemorySize, G1_SMEM);
        attr_set = true;
    }

    k_init<<<40, 256>>>();
    {
        int items1 = EE*2*W1N*(W1KP/4);
        k_conv1<<<(items1 + 255)/256, 256>>>(w1);
        int items2 = EE*512*(W2KP/4);
        k_conv2<<<(items2 + 255)/256, 256>>>(w2);
    }
    k_gate<<<BN/8, 256>>>(x, gw, png);
    k_scan<<<1, 1024>>>();
    k_gemm1<<<dim3((HH+127)/128, CAP/64, BE), 256, G1_SMEM>>>(b1, mb);
    k_gemm2<<<dim3(DD/128, CAP/64, BE), 256>>>(b2);
    k_combine<<<BN/8, 256>>>(x, lng, lnb, out);
    k_aux<<<1, 1>>>(out, out_size);
}